// round 1
// baseline (speedup 1.0000x reference)
#include <cuda_runtime.h>
#include <cuda_bf16.h>
#include <cstdint>

#define MAXN 2048
#define MARGIN 0.2f

// Scratch (no allocations allowed): dist matrix + row norms + accumulators
__device__ float  g_dist[(size_t)MAXN * MAXN];
__device__ float  g_sq[MAXN];
__device__ double g_acc[4];  // hinge_sum, prec_sum, pos_sum, neg_sum

// ---------------------------------------------------------------------------
__global__ void zero_acc_kernel() {
    if (threadIdx.x < 4) g_acc[threadIdx.x] = 0.0;
}

// ---------------------------------------------------------------------------
// Row squared norms: one warp per row (8 warps/block).
__global__ void sq_kernel(const float* __restrict__ x, int N, int D) {
    int warp = threadIdx.x / 32;
    int lane = threadIdx.x % 32;
    int row  = blockIdx.x * 8 + warp;
    if (row >= N) return;
    float s = 0.f;
    for (int k = lane; k < D; k += 32) {
        float v = x[row * D + k];
        s += v * v;
    }
    #pragma unroll
    for (int o = 16; o > 0; o >>= 1) s += __shfl_xor_sync(0xffffffffu, s, o);
    if (lane == 0) g_sq[row] = s;
}

// ---------------------------------------------------------------------------
// Tiled 64x64 dist tile per block. 256 threads, 4x4 microtile per thread.
// dist[i][j] = sqrt(max(sq_i + sq_j - 2*dot(x_i,x_j), 1e-12))
__global__ void dist_kernel(const float* __restrict__ x, int N, int D) {
    __shared__ float As[64][33];
    __shared__ float Bs[64][33];

    const int tx = threadIdx.x % 16;        // col group
    const int ty = threadIdx.x / 16;        // row group
    const int rowBase = blockIdx.y * 64;
    const int colBase = blockIdx.x * 64;

    float acc[4][4];
    #pragma unroll
    for (int i = 0; i < 4; i++)
        #pragma unroll
        for (int j = 0; j < 4; j++) acc[i][j] = 0.f;

    for (int kc = 0; kc < D; kc += 32) {
        // load 64 rows x 32 cols for A and B tiles; 512 float4 per tile
        for (int t = threadIdx.x; t < 64 * 8; t += 256) {
            int r  = t >> 3;
            int c4 = (t & 7) << 2;
            float4 va = *(const float4*)&x[(size_t)(rowBase + r) * D + kc + c4];
            As[r][c4 + 0] = va.x; As[r][c4 + 1] = va.y;
            As[r][c4 + 2] = va.z; As[r][c4 + 3] = va.w;
            float4 vb = *(const float4*)&x[(size_t)(colBase + r) * D + kc + c4];
            Bs[r][c4 + 0] = vb.x; Bs[r][c4 + 1] = vb.y;
            Bs[r][c4 + 2] = vb.z; Bs[r][c4 + 3] = vb.w;
        }
        __syncthreads();

        #pragma unroll
        for (int k = 0; k < 32; k++) {
            float a[4], b[4];
            #pragma unroll
            for (int i = 0; i < 4; i++) a[i] = As[ty * 4 + i][k];
            #pragma unroll
            for (int j = 0; j < 4; j++) b[j] = Bs[tx * 4 + j][k];
            #pragma unroll
            for (int i = 0; i < 4; i++)
                #pragma unroll
                for (int j = 0; j < 4; j++) acc[i][j] = fmaf(a[i], b[j], acc[i][j]);
        }
        __syncthreads();
    }

    #pragma unroll
    for (int i = 0; i < 4; i++) {
        int row = rowBase + ty * 4 + i;
        float sqr = g_sq[row];
        #pragma unroll
        for (int j = 0; j < 4; j++) {
            int col = colBase + tx * 4 + j;
            float d2 = sqr + g_sq[col] - 2.f * acc[i][j];
            g_dist[(size_t)row * N + col] = sqrtf(fmaxf(d2, 1e-12f));
        }
    }
}

// ---------------------------------------------------------------------------
// One block per anchor: collect positive distances, then scan negatives.
__global__ void hinge_kernel(const int* __restrict__ tg, int N) {
    const int i   = blockIdx.x;
    const int lbl = tg[i];
    const float* __restrict__ row = &g_dist[(size_t)i * N];

    __shared__ float s_pos[64];
    __shared__ int   s_np;
    __shared__ float s_red[4][8];

    if (threadIdx.x == 0) s_np = 0;
    __syncthreads();

    float pos_sum = 0.f;
    for (int j = threadIdx.x; j < N; j += blockDim.x) {
        if (j != i && tg[j] == lbl) {
            int p = atomicAdd(&s_np, 1);
            float d = row[j];
            if (p < 64) s_pos[p] = d;
            pos_sum += d;
        }
    }
    __syncthreads();
    const int np = min(s_np, 64);

    float hinge = 0.f, prec = 0.f, neg_sum = 0.f;
    for (int j = threadIdx.x; j < N; j += blockDim.x) {
        if (tg[j] != lbl) {
            float d = row[j];
            neg_sum += d;
            #pragma unroll 4
            for (int p = 0; p < np; p++) {
                float pd = s_pos[p];
                hinge += fmaxf(MARGIN + pd - d, 0.f);
                prec  += (d > pd) ? 1.f : 0.f;
            }
        }
    }

    // block reduction of (hinge, prec, pos_sum, neg_sum)
    float v[4] = {hinge, prec, pos_sum, neg_sum};
    int lane = threadIdx.x % 32, warp = threadIdx.x / 32;
    #pragma unroll
    for (int r = 0; r < 4; r++) {
        float s = v[r];
        #pragma unroll
        for (int o = 16; o > 0; o >>= 1) s += __shfl_xor_sync(0xffffffffu, s, o);
        if (lane == 0) s_red[r][warp] = s;
        v[r] = s;
    }
    __syncthreads();
    if (warp == 0) {
        int nw = blockDim.x / 32;
        #pragma unroll
        for (int r = 0; r < 4; r++) {
            float s = (lane < nw) ? s_red[r][lane] : 0.f;
            #pragma unroll
            for (int o = 4; o > 0; o >>= 1) s += __shfl_xor_sync(0xffffffffu, s, o);
            if (lane == 0) atomicAdd(&g_acc[r], (double)s);
        }
    }
}

// ---------------------------------------------------------------------------
__global__ void finalize_kernel(const int* __restrict__ ni, int N, float* __restrict__ out) {
    if (threadIdx.x != 0 || blockIdx.x != 0) return;
    int K = ni[0];
    double npos = (double)(K - 1);
    double nneg = (double)(N - K);
    double cnt  = (double)N * npos * nneg;
    out[0] = (float)(g_acc[0] / cnt);                 // loss
    out[1] = (float)(g_acc[1] / cnt);                 // prec
    out[2] = (float)(g_acc[2] / ((double)N * npos));  // pos_dist mean
    out[3] = (float)(g_acc[3] / ((double)N * nneg));  // neg_dist mean
}

// ---------------------------------------------------------------------------
extern "C" void kernel_launch(void* const* d_in, const int* in_sizes, int n_in,
                              void* d_out, int out_size) {
    const float* x  = (const float*)d_in[0];
    const int*   tg = (const int*)d_in[1];
    const int*   ni = (const int*)d_in[2];
    float*       out = (float*)d_out;

    const int N = in_sizes[1];
    const int D = in_sizes[0] / N;

    zero_acc_kernel<<<1, 32>>>();
    sq_kernel<<<(N + 7) / 8, 256>>>(x, N, D);
    dim3 grid(N / 64, N / 64);
    dist_kernel<<<grid, 256>>>(x, N, D);
    hinge_kernel<<<N, 256>>>(tg, N);
    finalize_kernel<<<1, 32>>>(ni, N, out);
}

// round 2
// speedup vs baseline: 1.7207x; 1.7207x over previous
#include <cuda_runtime.h>
#include <cuda_bf16.h>
#include <cstdint>

#define MAXN 2048
#define MARGIN 0.2f

__device__ float  g_dist[(size_t)MAXN * MAXN];
__device__ float  g_sq[MAXN];
__device__ double g_acc[4];  // hinge_sum, prec_sum, pos_sum, neg_sum

// ---------------------------------------------------------------------------
__global__ void zero_acc_kernel() {
    if (threadIdx.x < 4) g_acc[threadIdx.x] = 0.0;
}

// ---------------------------------------------------------------------------
// Row squared norms: one warp per row (8 warps/block).
__global__ void sq_kernel(const float* __restrict__ x, int N, int D) {
    int warp = threadIdx.x / 32;
    int lane = threadIdx.x % 32;
    int row  = blockIdx.x * 8 + warp;
    if (row >= N) return;
    float s = 0.f;
    for (int k = lane; k < D; k += 32) {
        float v = x[row * D + k];
        s += v * v;
    }
    #pragma unroll
    for (int o = 16; o > 0; o >>= 1) s += __shfl_xor_sync(0xffffffffu, s, o);
    if (lane == 0) g_sq[row] = s;
}

// ---------------------------------------------------------------------------
// tf32 mma.sync m16n8k8 helper. Raw f32 bits are truncated to tf32 by HW.
__device__ __forceinline__ void mma_tf32(float* c, const uint32_t* a, const uint32_t* b) {
    asm volatile(
        "mma.sync.aligned.m16n8k8.row.col.f32.tf32.tf32.f32 "
        "{%0,%1,%2,%3}, {%4,%5,%6,%7}, {%8,%9}, {%0,%1,%2,%3};\n"
        : "+f"(c[0]), "+f"(c[1]), "+f"(c[2]), "+f"(c[3])
        : "r"(a[0]), "r"(a[1]), "r"(a[2]), "r"(a[3]), "r"(b[0]), "r"(b[1]));
}

// ---------------------------------------------------------------------------
// Tensor-core dist kernel: 128x128 block tile, 8 warps (2x4), warp tile 64x32,
// tf32 m16n8k8 mma. dist[i][j] = sqrt(max(sq_i + sq_j - 2*dot, 1e-12))
__global__ __launch_bounds__(256)
void dist_mma_kernel(const float* __restrict__ x, int N, int D) {
    __shared__ float As[128][36];
    __shared__ float Bs[128][36];
    __shared__ float s_sqA[128], s_sqB[128];

    const int tid  = threadIdx.x;
    const int lane = tid & 31;
    const int warp = tid >> 5;
    const int wm   = warp >> 2;   // 0..1
    const int wn   = warp & 3;    // 0..3
    const int g    = lane >> 2;   // 0..7
    const int q    = lane & 3;    // 0..3

    const int rowBase = blockIdx.y * 128;
    const int colBase = blockIdx.x * 128;

    if (tid < 128) {
        s_sqA[tid] = g_sq[rowBase + tid];
        s_sqB[tid] = g_sq[colBase + tid];
    }

    float acc[4][4][4];
    #pragma unroll
    for (int mt = 0; mt < 4; mt++)
        #pragma unroll
        for (int nt = 0; nt < 4; nt++)
            #pragma unroll
            for (int r = 0; r < 4; r++) acc[mt][nt][r] = 0.f;

    for (int kc = 0; kc < D; kc += 32) {
        __syncthreads();
        // stage A (rows) and B (cols) tiles: 128 x 32 each, float4 loads
        for (int t = tid; t < 128 * 8; t += 256) {
            int r  = t >> 3;
            int c4 = (t & 7) << 2;
            float4 va = *(const float4*)&x[(size_t)(rowBase + r) * D + kc + c4];
            *(float4*)&As[r][c4] = va;
            float4 vb = *(const float4*)&x[(size_t)(colBase + r) * D + kc + c4];
            *(float4*)&Bs[r][c4] = vb;
        }
        __syncthreads();

        #pragma unroll
        for (int kk = 0; kk < 32; kk += 8) {
            uint32_t a[4][4];
            #pragma unroll
            for (int mt = 0; mt < 4; mt++) {
                int r0 = wm * 64 + mt * 16 + g;
                a[mt][0] = __float_as_uint(As[r0][kk + q]);
                a[mt][1] = __float_as_uint(As[r0 + 8][kk + q]);
                a[mt][2] = __float_as_uint(As[r0][kk + q + 4]);
                a[mt][3] = __float_as_uint(As[r0 + 8][kk + q + 4]);
            }
            uint32_t b[4][2];
            #pragma unroll
            for (int nt = 0; nt < 4; nt++) {
                int c0 = wn * 32 + nt * 8 + g;
                b[nt][0] = __float_as_uint(Bs[c0][kk + q]);
                b[nt][1] = __float_as_uint(Bs[c0][kk + q + 4]);
            }
            #pragma unroll
            for (int mt = 0; mt < 4; mt++)
                #pragma unroll
                for (int nt = 0; nt < 4; nt++)
                    mma_tf32(acc[mt][nt], a[mt], b[nt]);
        }
    }

    // epilogue
    #pragma unroll
    for (int mt = 0; mt < 4; mt++) {
        int r0 = wm * 64 + mt * 16 + g;
        float sq0 = s_sqA[r0];
        float sq1 = s_sqA[r0 + 8];
        #pragma unroll
        for (int nt = 0; nt < 4; nt++) {
            int c0 = wn * 32 + nt * 8 + 2 * q;
            float sc0 = s_sqB[c0];
            float sc1 = s_sqB[c0 + 1];
            float d00 = sqrtf(fmaxf(sq0 + sc0 - 2.f * acc[mt][nt][0], 1e-12f));
            float d01 = sqrtf(fmaxf(sq0 + sc1 - 2.f * acc[mt][nt][1], 1e-12f));
            float d10 = sqrtf(fmaxf(sq1 + sc0 - 2.f * acc[mt][nt][2], 1e-12f));
            float d11 = sqrtf(fmaxf(sq1 + sc1 - 2.f * acc[mt][nt][3], 1e-12f));
            *(float2*)&g_dist[(size_t)(rowBase + r0) * N + colBase + c0] = make_float2(d00, d01);
            *(float2*)&g_dist[(size_t)(rowBase + r0 + 8) * N + colBase + c0] = make_float2(d10, d11);
        }
    }
}

// ---------------------------------------------------------------------------
// One block per anchor. Positives in registers; hinge via
// sum relu(delta) = 0.5*(sum delta + sum |delta|), sum delta in closed form.
__global__ __launch_bounds__(256)
void hinge_kernel(const int* __restrict__ tg, int N) {
    const int i   = blockIdx.x;
    const int lbl = tg[i];
    const float* __restrict__ row = &g_dist[(size_t)i * N];

    __shared__ float s_pos[64];
    __shared__ int   s_np;
    __shared__ float s_red[4][8];

    if (threadIdx.x == 0) s_np = 0;
    __syncthreads();

    // pass 1: collect positives (order irrelevant — all stats are symmetric sums)
    for (int j = threadIdx.x; j < N; j += blockDim.x) {
        if (j != i && tg[j] == lbl) {
            int p = atomicAdd(&s_np, 1);
            if (p < 64) s_pos[p] = row[j];
        }
    }
    __syncthreads();
    const int np = min(s_np, 64);

    float sabs = 0.f;   // sum |0.2 + pd - nd|
    float dn   = 0.f;   // sum of negative distances
    int   pc   = 0;     // precision count (nd > pd)

    const float4* __restrict__ row4 = (const float4*)row;
    const int4*   __restrict__ tg4  = (const int4*)tg;

    if (np == 7) {
        float t0 = s_pos[0] + MARGIN, t1 = s_pos[1] + MARGIN, t2 = s_pos[2] + MARGIN;
        float t3 = s_pos[3] + MARGIN, t4 = s_pos[4] + MARGIN, t5 = s_pos[5] + MARGIN;
        float t6 = s_pos[6] + MARGIN;
        #define PAIR7(t, d) { float dl = (t) - (d); sabs += fabsf(dl); pc += (dl < MARGIN); }
        for (int j4 = threadIdx.x; j4 < (N >> 2); j4 += blockDim.x) {
            float4 d4 = row4[j4];
            int4   l4 = tg4[j4];
            if (l4.x != lbl) { dn += d4.x; PAIR7(t0,d4.x) PAIR7(t1,d4.x) PAIR7(t2,d4.x) PAIR7(t3,d4.x) PAIR7(t4,d4.x) PAIR7(t5,d4.x) PAIR7(t6,d4.x) }
            if (l4.y != lbl) { dn += d4.y; PAIR7(t0,d4.y) PAIR7(t1,d4.y) PAIR7(t2,d4.y) PAIR7(t3,d4.y) PAIR7(t4,d4.y) PAIR7(t5,d4.y) PAIR7(t6,d4.y) }
            if (l4.z != lbl) { dn += d4.z; PAIR7(t0,d4.z) PAIR7(t1,d4.z) PAIR7(t2,d4.z) PAIR7(t3,d4.z) PAIR7(t4,d4.z) PAIR7(t5,d4.z) PAIR7(t6,d4.z) }
            if (l4.w != lbl) { dn += d4.w; PAIR7(t0,d4.w) PAIR7(t1,d4.w) PAIR7(t2,d4.w) PAIR7(t3,d4.w) PAIR7(t4,d4.w) PAIR7(t5,d4.w) PAIR7(t6,d4.w) }
        }
        #undef PAIR7
    } else {
        for (int j = threadIdx.x; j < N; j += blockDim.x) {
            if (tg[j] != lbl) {
                float d = row[j];
                dn += d;
                for (int p = 0; p < np; p++) {
                    float dl = s_pos[p] + MARGIN - d;
                    sabs += fabsf(dl);
                    pc += (dl < MARGIN);
                }
            }
        }
    }

    // block reduction of (sabs, dn, pc)
    float v[3] = {sabs, dn, (float)pc};
    int lane = threadIdx.x & 31, warp = threadIdx.x >> 5;
    #pragma unroll
    for (int r = 0; r < 3; r++) {
        float s = v[r];
        #pragma unroll
        for (int o = 16; o > 0; o >>= 1) s += __shfl_xor_sync(0xffffffffu, s, o);
        if (lane == 0) s_red[r][warp] = s;
    }
    __syncthreads();
    if (warp == 0 && lane < 3) {
        // one lane per quantity reduces 8 warp partials serially (cheap)
        float s = 0.f;
        #pragma unroll
        for (int w = 0; w < 8; w++) s += s_red[lane][w];
        s_red[lane][0] = s;
    }
    __syncthreads();
    if (threadIdx.x == 0) {
        double sabs_t = (double)s_red[0][0];
        double dn_t   = (double)s_red[1][0];
        double pc_t   = (double)s_red[2][0];
        double possum = 0.0;
        for (int p = 0; p < np; p++) possum += (double)s_pos[p];
        double nneg = (double)(N - np - 1);
        double T    = possum + (double)np * (double)MARGIN;
        double hinge = 0.5 * (nneg * T - (double)np * dn_t + sabs_t);
        atomicAdd(&g_acc[0], hinge);
        atomicAdd(&g_acc[1], pc_t);
        atomicAdd(&g_acc[2], possum);
        atomicAdd(&g_acc[3], dn_t);
    }
}

// ---------------------------------------------------------------------------
__global__ void finalize_kernel(const int* __restrict__ ni, int N, float* __restrict__ out) {
    if (threadIdx.x != 0 || blockIdx.x != 0) return;
    int K = ni[0];
    double npos = (double)(K - 1);
    double nneg = (double)(N - K);
    double cnt  = (double)N * npos * nneg;
    out[0] = (float)(g_acc[0] / cnt);                 // loss
    out[1] = (float)(g_acc[1] / cnt);                 // prec
    out[2] = (float)(g_acc[2] / ((double)N * npos));  // pos_dist mean
    out[3] = (float)(g_acc[3] / ((double)N * nneg));  // neg_dist mean
}

// ---------------------------------------------------------------------------
extern "C" void kernel_launch(void* const* d_in, const int* in_sizes, int n_in,
                              void* d_out, int out_size) {
    const float* x  = (const float*)d_in[0];
    const int*   tg = (const int*)d_in[1];
    const int*   ni = (const int*)d_in[2];
    float*       out = (float*)d_out;

    const int N = in_sizes[1];
    const int D = in_sizes[0] / N;

    zero_acc_kernel<<<1, 32>>>();
    sq_kernel<<<(N + 7) / 8, 256>>>(x, N, D);
    dim3 grid(N / 128, N / 128);
    dist_mma_kernel<<<grid, 256>>>(x, N, D);
    hinge_kernel<<<N, 256>>>(tg, N);
    finalize_kernel<<<1, 32>>>(ni, N, out);
}